// round 7
// baseline (speedup 1.0000x reference)
#include <cuda_runtime.h>
#include <cuda_fp16.h>

#define BB 256   // batch
#define SS 256   // seq len / steps
#define DD 128   // decoder dim
#define GG 512   // 4*D gates
#define TN 512   // lookup-table intervals

// fp16x2-packed LSTM hidden weights, warp-coalesced block layout:
// uint4 block (j,u): j=0..15 (k-range [8j,8j+8)), u=0..511 (gate).
// word m of block = half2{ W_hh[u][8j+2m], W_hh[u][8j+2m+1] }.
// flat uint index = (j*512 + u)*4 + m.  Total 128 KB -> L1-resident.
__device__ __align__(16) unsigned int g_Wpack[32768];
__device__ float g_w1sum[SS];
__device__ float g_bias[GG];

__device__ __forceinline__ float tanh_fast(float x) {
    float y;
    asm("tanh.approx.f32 %0, %1;" : "=f"(y) : "f"(x));
    return y;
}
__device__ __forceinline__ float sigmoid_fast(float x) {
    return fmaf(tanh_fast(0.5f * x), 0.5f, 0.5f);
}
__device__ __forceinline__ unsigned long long pack2(float a, float b) {
    unsigned long long r;
    asm("mov.b64 %0, {%1,%2};" : "=l"(r) : "f"(a), "f"(b));
    return r;
}

// ---------------------------------------------------------------------------
// Prep kernel: pack W_hh to fp16 blocks, row-sum W1_w, fuse biases. One-time.
// ---------------------------------------------------------------------------
__global__ void prep_kernel(const float* __restrict__ W1_w,
                            const float* __restrict__ W_hh,
                            const float* __restrict__ b_ih,
                            const float* __restrict__ b_hh) {
    int blk = blockIdx.x;
    int t = threadIdx.x;
    if (blk < 128) {
        int idx = blk * 256 + t;          // 0..32767
        int j = idx >> 11;                // k-block 0..15
        int u = (idx >> 2) & 511;         // gate
        int m = idx & 3;
        int k0 = 8 * j + 2 * m;
        __half2 v = __halves2half2(__float2half_rn(W_hh[u * DD + k0]),
                                   __float2half_rn(W_hh[u * DD + k0 + 1]));
        g_Wpack[idx] = *(unsigned int*)&v;
    } else {
        int lane = t & 31, w = t >> 5;
        for (int r = 0; r < 32; r++) {
            int s = w * 32 + r;
            float acc = 0.f;
            #pragma unroll
            for (int i = 0; i < 8; i++) acc += W1_w[s * SS + lane + 32 * i];
            #pragma unroll
            for (int off = 16; off; off >>= 1)
                acc += __shfl_xor_sync(0xffffffffu, acc, off);
            if (lane == 0) g_w1sum[s] = acc;
        }
        g_bias[t]       = b_ih[t]       + b_hh[t];
        g_bias[t + 256] = b_ih[t + 256] + b_hh[t + 256];
    }
}

// ---------------------------------------------------------------------------
// Main kernel: 2 batch elements per CTA, 1024 threads, 256 LSTM steps.
// Attention collapsed to per-batch 1-D lerp table g(h) built once.
// Lane parity = batch -> each weight word fetched once per warp (broadcast).
// 2 barriers per step.
// ---------------------------------------------------------------------------
__global__ __launch_bounds__(1024, 1)
void decoder_kernel(const float* __restrict__ enc,   // [B,S,E]
                    const float* __restrict__ W1_b,  // [S]
                    const float* __restrict__ W2_w,  // [S,2S]
                    const float* __restrict__ W2_b,  // [S]
                    const float* __restrict__ W_ih,  // [4D,E]
                    float* __restrict__ out)         // [S,B,D]
{
    __shared__ __align__(16) float4 sAC[2][128];   // per batch: {a(2p),a(2p+1),c(2p),c(2p+1)}
    __shared__ __align__(16) float4 sE[2][128];    // per batch: {e0(2p),e0(2p+1),e1(2p),e1(2p+1)}
    __shared__ __align__(16) float  ebuf[1024];    // [m][512] flattened encoders
    __shared__ float a_st[2][256];
    __shared__ __align__(16) float4 Ttab[2][TN];   // {g0x,g0y,dgx,dgy}
    __shared__ float2 tail2[2];
    __shared__ float gates_s[2][GG];
    __shared__ __align__(16) float h_s[2][DD];
    __shared__ float c_s[2][DD];
    __shared__ __align__(16) float2 wred[2][4];
    __shared__ __align__(16) float2 wihs[GG];      // W_ih rows as float2

    const int bid = blockIdx.x;
    const int t = threadIdx.x;        // 0..1023
    const int lane = t & 31;
    const int warp = t >> 5;

    // ---- init loads ----
    ebuf[t] = enc[bid * 1024 + t];                 // two batches, contiguous
    if (t < GG) wihs[t] = ((const float2*)W_ih)[t];
    if (t < 256) { ((float*)h_s)[t] = 0.f; ((float*)c_s)[t] = 0.f; }
    __syncthreads();

    // a[m][s] = encflat[m] . W2_w[s,:] + W2_b[s] + W1_b[s]
    {
        const int m_w = warp >> 4;                  // warps 0-15: batch0, 16-31: batch1
        const float4* W2w4 = (const float4*)W2_w;
        const float4* e4   = (const float4*)(ebuf + m_w * 512);
        for (int r = 0; r < 16; r++) {
            int s = (warp & 15) * 16 + r;
            float acc = 0.f;
            #pragma unroll
            for (int i = 0; i < 4; i++) {
                float4 wv = W2w4[s * 128 + lane + 32 * i];
                float4 ev = e4[lane + 32 * i];
                acc += wv.x * ev.x + wv.y * ev.y + wv.z * ev.z + wv.w * ev.w;
            }
            #pragma unroll
            for (int off = 16; off; off >>= 1)
                acc += __shfl_xor_sync(0xffffffffu, acc, off);
            if (lane == 0) a_st[m_w][s] = acc + W2_b[s] + W1_b[s];
        }
    }
    __syncthreads();
    if (t < 256) {
        int m = t >> 7, p = t & 127;
        sAC[m][p] = make_float4(a_st[m][2 * p], a_st[m][2 * p + 1],
                                g_w1sum[2 * p], g_w1sum[2 * p + 1]);
        sE[m][p]  = make_float4(ebuf[m * 512 + 4 * p],     ebuf[m * 512 + 4 * p + 2],
                                ebuf[m * 512 + 4 * p + 1], ebuf[m * 512 + 4 * p + 3]);
    }
    __syncthreads();

    // Degree-5 Chebyshev-economized poly for exp(t), t in [-1,1], abs err <= 5e-5
    const unsigned long long P5 = pack2(0.00868688f, 0.00868688f);
    const unsigned long long P4 = pack2(0.04379392f, 0.04379392f);
    const unsigned long long P3 = pack2(0.16648880f, 0.16648880f);
    const unsigned long long P2 = pack2(0.49919676f, 0.49919676f);
    const unsigned long long P1 = pack2(1.00002231f, 1.00002231f);
    const unsigned long long P0 = pack2(1.00004478f, 1.00004478f);

    // ---- build lookup tables: nodes k = 0..TN for each batch m ----
    for (int idx = t; idx < 2 * (TN + 1); idx += 1024) {
        int m = (idx > TN) ? 1 : 0;
        int k = idx - m * (TN + 1);
        const double2* pAC = (const double2*)sAC[m];
        const double2* pE  = (const double2*)sE[m];
        float h = fmaf((float)k, 2.0f / TN, -1.0f);
        unsigned long long hd2;
        asm("mov.b64 %0, {%1,%1};" : "=l"(hd2) : "f"(h));
        unsigned long long Z2 = 0ull, n02 = 0ull, n12 = 0ull;
        #pragma unroll 4
        for (int i = 0; i < 128; i++) {
            double2 acd = pAC[i];
            double2 eed = pE[i];
            unsigned long long ap  = __double_as_longlong(acd.x);
            unsigned long long cp  = __double_as_longlong(acd.y);
            unsigned long long e0p = __double_as_longlong(eed.x);
            unsigned long long e1p = __double_as_longlong(eed.y);
            unsigned long long x2;
            asm("fma.rn.f32x2 %0, %1, %2, %3;" : "=l"(x2) : "l"(hd2), "l"(cp), "l"(ap));
            float x0, x1;
            asm("mov.b64 {%0,%1}, %2;" : "=f"(x0), "=f"(x1) : "l"(x2));
            float t0 = tanh_fast(x0);
            float t1 = tanh_fast(x1);
            unsigned long long t2;
            asm("mov.b64 %0, {%1,%2};" : "=l"(t2) : "f"(t0), "f"(t1));
            unsigned long long p;
            asm("fma.rn.f32x2 %0, %1, %2, %3;" : "=l"(p) : "l"(P5), "l"(t2), "l"(P4));
            asm("fma.rn.f32x2 %0, %0, %1, %2;" : "+l"(p) : "l"(t2), "l"(P3));
            asm("fma.rn.f32x2 %0, %0, %1, %2;" : "+l"(p) : "l"(t2), "l"(P2));
            asm("fma.rn.f32x2 %0, %0, %1, %2;" : "+l"(p) : "l"(t2), "l"(P1));
            asm("fma.rn.f32x2 %0, %0, %1, %2;" : "+l"(p) : "l"(t2), "l"(P0));
            asm("add.rn.f32x2 %0, %0, %1;"     : "+l"(Z2) : "l"(p));
            asm("fma.rn.f32x2 %0, %1, %2, %0;" : "+l"(n02) : "l"(p), "l"(e0p));
            asm("fma.rn.f32x2 %0, %1, %2, %0;" : "+l"(n12) : "l"(p), "l"(e1p));
        }
        float Zl, Zh, a0, a1, b0, b1;
        asm("mov.b64 {%0,%1}, %2;" : "=f"(Zl), "=f"(Zh) : "l"(Z2));
        asm("mov.b64 {%0,%1}, %2;" : "=f"(a0), "=f"(a1) : "l"(n02));
        asm("mov.b64 {%0,%1}, %2;" : "=f"(b0), "=f"(b1) : "l"(n12));
        float Z = Zl + Zh, n0 = a0 + a1, n1 = b0 + b1;
        float inv = __fdividef(1.f, Z);
        float gx = n0 * inv, gy = n1 * inv;
        if (k < TN) { Ttab[m][k].x = gx; Ttab[m][k].y = gy; }
        else        { tail2[m] = make_float2(gx, gy); }
    }
    __syncthreads();
    // pass 2: slopes (exactly 1024 items = 1 per thread)
    {
        int m = t >> 9, k = t & (TN - 1);
        float2 cur = *(const float2*)&Ttab[m][k];
        float2 nxt = (k == TN - 1) ? tail2[m] : *(const float2*)&Ttab[m][k + 1];
        __syncthreads();
        Ttab[m][k].z = nxt.x - cur.x;
        Ttab[m][k].w = nxt.y - cur.y;
    }
    __syncthreads();

    // thread roles: gate u, batch mb
    const int u  = warp * 16 + (lane >> 1);   // 0..511
    const int mb = lane & 1;                  // 0/1
    const float bias = g_bias[u];
    const uint4* Wq4 = ((const uint4*)g_Wpack) + u;
    const float4* h4 = (const float4*)h_s[mb];

    for (int step = 0; step < SS; step++) {
        // ---- Phase 1a: attention lookup (threads 0..255: one (m,d) each) ----
        if (t < 256) {
            int m = t >> 7, d = t & 127;
            float h = h_s[m][d];
            float uu = fmaf(h, (float)(TN / 2), (float)(TN / 2));
            int i = (int)uu;
            i = max(0, min(i, TN - 1));
            float f = uu - (float)i;
            float4 tv = Ttab[m][i];
            float gx = fmaf(f, tv.z, tv.x);
            float gy = fmaf(f, tv.w, tv.y);
            #pragma unroll
            for (int off = 16; off; off >>= 1) {
                gx += __shfl_xor_sync(0xffffffffu, gx, off);
                gy += __shfl_xor_sync(0xffffffffu, gy, off);
            }
            if (lane == 0) wred[m][warp & 3] = make_float2(gx, gy);
        }

        // ---- Phase 1b: LSTM h-dot (all threads; weights deduped per warp) ----
        float acc0 = bias, acc1 = 0.f;
        #pragma unroll 4
        for (int j = 0; j < 16; j++) {
            uint4 wr = Wq4[j * 512];            // LDG.128, broadcast to lane pair
            float4 hA = h4[2 * j];              // LDS broadcast (per batch)
            float4 hB = h4[2 * j + 1];
            float2 f0 = __half22float2(*(const __half2*)&wr.x);
            float2 f1 = __half22float2(*(const __half2*)&wr.y);
            float2 f2 = __half22float2(*(const __half2*)&wr.z);
            float2 f3 = __half22float2(*(const __half2*)&wr.w);
            acc0 = fmaf(hA.x, f0.x, acc0);
            acc1 = fmaf(hA.y, f0.y, acc1);
            acc0 = fmaf(hA.z, f1.x, acc0);
            acc1 = fmaf(hA.w, f1.y, acc1);
            acc0 = fmaf(hB.x, f2.x, acc0);
            acc1 = fmaf(hB.y, f2.y, acc1);
            acc0 = fmaf(hB.z, f3.x, acc0);
            acc1 = fmaf(hB.w, f3.y, acc1);
        }
        gates_s[mb][u] = acc0 + acc1;
        __syncthreads();                         // B1

        // ---- Phase 2: ctx-combine + LSTM update (threads 0..255) ----
        if (t < 256) {
            int m = t >> 7, d = t & 127;
            float2 r0 = wred[m][0], r1 = wred[m][1], r2 = wred[m][2], r3 = wred[m][3];
            float x0c = (r0.x + r1.x + r2.x + r3.x) * (1.f / 128.f);
            float x1c = (r0.y + r1.y + r2.y + r3.y) * (1.f / 128.f);
            float2 wi0 = wihs[d];
            float2 wi1 = wihs[d + 128];
            float2 wi2 = wihs[d + 256];
            float2 wi3 = wihs[d + 384];
            float gi = gates_s[m][d]       + x0c * wi0.x + x1c * wi0.y;
            float gf = gates_s[m][d + 128] + x0c * wi1.x + x1c * wi1.y;
            float gg = gates_s[m][d + 256] + x0c * wi2.x + x1c * wi2.y;
            float go = gates_s[m][d + 384] + x0c * wi3.x + x1c * wi3.y;
            float si = sigmoid_fast(gi);
            float sf = sigmoid_fast(gf);
            float so = sigmoid_fast(go);
            float c = fmaf(sf, c_s[m][d], si * tanh_fast(gg));
            float h = so * tanh_fast(c);
            c_s[m][d] = c;
            h_s[m][d] = h;
            out[(size_t)step * (BB * DD) + (2 * bid + m) * DD + d] = h;
        }
        __syncthreads();                         // B2
    }
}

// ---------------------------------------------------------------------------
extern "C" void kernel_launch(void* const* d_in, const int* in_sizes, int n_in,
                              void* d_out, int out_size) {
    const float* enc  = (const float*)d_in[0];
    const float* W1_w = (const float*)d_in[1];
    const float* W1_b = (const float*)d_in[2];
    const float* W2_w = (const float*)d_in[3];
    const float* W2_b = (const float*)d_in[4];
    const float* W_ih = (const float*)d_in[5];
    const float* W_hh = (const float*)d_in[6];
    const float* b_ih = (const float*)d_in[7];
    const float* b_hh = (const float*)d_in[8];
    float* out = (float*)d_out;

    prep_kernel<<<129, 256>>>(W1_w, W_hh, b_ih, b_hh);
    decoder_kernel<<<BB / 2, 1024>>>(enc, W1_b, W2_w, W2_b, W_ih, out);
}

// round 8
// speedup vs baseline: 1.4226x; 1.4226x over previous
#include <cuda_runtime.h>
#include <cuda_fp16.h>

#define BB 256   // batch
#define SS 256   // seq len / steps
#define DD 128   // decoder dim
#define GG 512   // 4*D gates
#define TN 512   // lookup-table intervals

// fp16x2 LSTM hidden weights, register-load layout:
// uint idx = kh*16384 + j*512 + u :  half2{ W_hh[u][kh*64+2j], W_hh[u][kh*64+2j+1] }
// (u = gate 0..511, kh = k-half 0/1, j = 0..31). 128 KB total.
__device__ __align__(16) unsigned int g_Wpack[32768];
__device__ float g_w1sum[SS];
__device__ float g_bias[GG];

__device__ __forceinline__ float tanh_fast(float x) {
    float y;
    asm("tanh.approx.f32 %0, %1;" : "=f"(y) : "f"(x));
    return y;
}
__device__ __forceinline__ float sigmoid_fast(float x) {
    return fmaf(tanh_fast(0.5f * x), 0.5f, 0.5f);
}
__device__ __forceinline__ unsigned long long pack2(float a, float b) {
    unsigned long long r;
    asm("mov.b64 %0, {%1,%2};" : "=l"(r) : "f"(a), "f"(b));
    return r;
}

// ---------------------------------------------------------------------------
// Prep kernel: pack W_hh, row-sum W1_w, fuse biases. One-time.
// ---------------------------------------------------------------------------
__global__ void prep_kernel(const float* __restrict__ W1_w,
                            const float* __restrict__ W_hh,
                            const float* __restrict__ b_ih,
                            const float* __restrict__ b_hh) {
    int blk = blockIdx.x;
    int t = threadIdx.x;
    if (blk < 128) {
        int idx = blk * 256 + t;          // 0..32767
        int u  = idx & 511;
        int j  = (idx >> 9) & 31;
        int kh = idx >> 14;
        int k0 = kh * 64 + 2 * j;
        __half2 v = __halves2half2(__float2half_rn(W_hh[u * DD + k0]),
                                   __float2half_rn(W_hh[u * DD + k0 + 1]));
        g_Wpack[idx] = *(unsigned int*)&v;
    } else {
        int lane = t & 31, w = t >> 5;
        for (int r = 0; r < 32; r++) {
            int s = w * 32 + r;
            float acc = 0.f;
            #pragma unroll
            for (int i = 0; i < 8; i++) acc += W1_w[s * SS + lane + 32 * i];
            #pragma unroll
            for (int off = 16; off; off >>= 1)
                acc += __shfl_xor_sync(0xffffffffu, acc, off);
            if (lane == 0) g_w1sum[s] = acc;
        }
        g_bias[t]       = b_ih[t]       + b_hh[t];
        g_bias[t + 256] = b_ih[t + 256] + b_hh[t + 256];
    }
}

// ---------------------------------------------------------------------------
// Main kernel: 2 batch elements per CTA, 1024 threads, 256 LSTM steps.
// Attention collapsed to per-batch lerp tables (built once).
// LSTM weights live in REGISTERS: thread = (gate u, k-half kh), 32 half2 regs.
// ---------------------------------------------------------------------------
__global__ __launch_bounds__(1024, 1)
void decoder_kernel(const float* __restrict__ enc,   // [B,S,E]
                    const float* __restrict__ W1_b,  // [S]
                    const float* __restrict__ W2_w,  // [S,2S]
                    const float* __restrict__ W2_b,  // [S]
                    const float* __restrict__ W_ih,  // [4D,E]
                    float* __restrict__ out)         // [S,B,D]
{
    __shared__ __align__(16) float4 sAC[2][128];
    __shared__ __align__(16) float4 sE[2][128];
    __shared__ __align__(16) float  ebuf[1024];
    __shared__ float a_st[2][256];
    __shared__ __align__(16) float4 Ttab[2][TN];   // {g0x,g0y,dgx,dgy}
    __shared__ float2 tail2[2];
    __shared__ float gph[2][2][GG];                // [kh][m][u] partial gates
    __shared__ __align__(16) float h_s[2][DD];
    __shared__ __align__(16) float2 wred[2][4];
    __shared__ __align__(16) float2 wihs[GG];
    __shared__ float sbias[GG];

    const int bid = blockIdx.x;
    const int t = threadIdx.x;        // 0..1023
    const int lane = t & 31;
    const int warp = t >> 5;

    // ---- init loads ----
    ebuf[t] = enc[bid * 1024 + t];
    if (t < GG) { wihs[t] = ((const float2*)W_ih)[t]; sbias[t] = g_bias[t]; }
    if (t < 256) h_s[t >> 7][t & 127] = 0.f;
    __syncthreads();

    // a[m][s] = encflat[m] . W2_w[s,:] + W2_b[s] + W1_b[s]
    {
        const int m_w = warp >> 4;
        const float4* W2w4 = (const float4*)W2_w;
        const float4* e4   = (const float4*)(ebuf + m_w * 512);
        for (int r = 0; r < 16; r++) {
            int s = (warp & 15) * 16 + r;
            float acc = 0.f;
            #pragma unroll
            for (int i = 0; i < 4; i++) {
                float4 wv = W2w4[s * 128 + lane + 32 * i];
                float4 ev = e4[lane + 32 * i];
                acc += wv.x * ev.x + wv.y * ev.y + wv.z * ev.z + wv.w * ev.w;
            }
            #pragma unroll
            for (int off = 16; off; off >>= 1)
                acc += __shfl_xor_sync(0xffffffffu, acc, off);
            if (lane == 0) a_st[m_w][s] = acc + W2_b[s] + W1_b[s];
        }
    }
    __syncthreads();
    if (t < 256) {
        int m = t >> 7, p = t & 127;
        sAC[m][p] = make_float4(a_st[m][2 * p], a_st[m][2 * p + 1],
                                g_w1sum[2 * p], g_w1sum[2 * p + 1]);
        sE[m][p]  = make_float4(ebuf[m * 512 + 4 * p],     ebuf[m * 512 + 4 * p + 2],
                                ebuf[m * 512 + 4 * p + 1], ebuf[m * 512 + 4 * p + 3]);
    }
    __syncthreads();

    // Degree-5 Chebyshev-economized poly for exp(t), t in [-1,1], abs err <= 5e-5
    const unsigned long long P5 = pack2(0.00868688f, 0.00868688f);
    const unsigned long long P4 = pack2(0.04379392f, 0.04379392f);
    const unsigned long long P3 = pack2(0.16648880f, 0.16648880f);
    const unsigned long long P2 = pack2(0.49919676f, 0.49919676f);
    const unsigned long long P1 = pack2(1.00002231f, 1.00002231f);
    const unsigned long long P0 = pack2(1.00004478f, 1.00004478f);

    // ---- build lookup tables ----
    for (int idx = t; idx < 2 * (TN + 1); idx += 1024) {
        int m = (idx > TN) ? 1 : 0;
        int k = idx - m * (TN + 1);
        const double2* pAC = (const double2*)sAC[m];
        const double2* pE  = (const double2*)sE[m];
        float h = fmaf((float)k, 2.0f / TN, -1.0f);
        unsigned long long hd2;
        asm("mov.b64 %0, {%1,%1};" : "=l"(hd2) : "f"(h));
        unsigned long long Z2 = 0ull, n02 = 0ull, n12 = 0ull;
        #pragma unroll 4
        for (int i = 0; i < 128; i++) {
            double2 acd = pAC[i];
            double2 eed = pE[i];
            unsigned long long ap  = __double_as_longlong(acd.x);
            unsigned long long cp  = __double_as_longlong(acd.y);
            unsigned long long e0p = __double_as_longlong(eed.x);
            unsigned long long e1p = __double_as_longlong(eed.y);
            unsigned long long x2;
            asm("fma.rn.f32x2 %0, %1, %2, %3;" : "=l"(x2) : "l"(hd2), "l"(cp), "l"(ap));
            float x0, x1;
            asm("mov.b64 {%0,%1}, %2;" : "=f"(x0), "=f"(x1) : "l"(x2));
            float t0 = tanh_fast(x0);
            float t1 = tanh_fast(x1);
            unsigned long long t2;
            asm("mov.b64 %0, {%1,%2};" : "=l"(t2) : "f"(t0), "f"(t1));
            unsigned long long p;
            asm("fma.rn.f32x2 %0, %1, %2, %3;" : "=l"(p) : "l"(P5), "l"(t2), "l"(P4));
            asm("fma.rn.f32x2 %0, %0, %1, %2;" : "+l"(p) : "l"(t2), "l"(P3));
            asm("fma.rn.f32x2 %0, %0, %1, %2;" : "+l"(p) : "l"(t2), "l"(P2));
            asm("fma.rn.f32x2 %0, %0, %1, %2;" : "+l"(p) : "l"(t2), "l"(P1));
            asm("fma.rn.f32x2 %0, %0, %1, %2;" : "+l"(p) : "l"(t2), "l"(P0));
            asm("add.rn.f32x2 %0, %0, %1;"     : "+l"(Z2) : "l"(p));
            asm("fma.rn.f32x2 %0, %1, %2, %0;" : "+l"(n02) : "l"(p), "l"(e0p));
            asm("fma.rn.f32x2 %0, %1, %2, %0;" : "+l"(n12) : "l"(p), "l"(e1p));
        }
        float Zl, Zh, a0, a1, b0, b1;
        asm("mov.b64 {%0,%1}, %2;" : "=f"(Zl), "=f"(Zh) : "l"(Z2));
        asm("mov.b64 {%0,%1}, %2;" : "=f"(a0), "=f"(a1) : "l"(n02));
        asm("mov.b64 {%0,%1}, %2;" : "=f"(b0), "=f"(b1) : "l"(n12));
        float Z = Zl + Zh, n0 = a0 + a1, n1 = b0 + b1;
        float inv = __fdividef(1.f, Z);
        float gx = n0 * inv, gy = n1 * inv;
        if (k < TN) { Ttab[m][k].x = gx; Ttab[m][k].y = gy; }
        else        { tail2[m] = make_float2(gx, gy); }
    }
    __syncthreads();
    {   // slopes: exactly 1024 items = 1 per thread
        int m = t >> 9, k = t & (TN - 1);
        float2 cur = *(const float2*)&Ttab[m][k];
        float2 nxt = (k == TN - 1) ? tail2[m] : *(const float2*)&Ttab[m][k + 1];
        __syncthreads();
        Ttab[m][k].z = nxt.x - cur.x;
        Ttab[m][k].w = nxt.y - cur.y;
    }
    __syncthreads();

    // ---- roles + register weight load ----
    const int u  = t & 511;           // gate
    const int kh = t >> 9;            // k-half (warp-uniform)
    unsigned int Wr[32];
    {
        const unsigned int* wsrc = g_Wpack + kh * 16384 + u;
        #pragma unroll
        for (int j = 0; j < 32; j++) Wr[j] = wsrc[j * 512];   // coalesced, one-time
    }
    float c_reg = 0.f, h_reg = 0.f;   // LSTM state for epilogue threads (0..255)

    const float4* h40 = (const float4*)(h_s[0]) + (kh << 4);
    const float4* h41 = (const float4*)(h_s[1]) + (kh << 4);

    for (int step = 0; step < SS; step++) {
        // ---- Phase 1a: h-dot (all threads; weights in registers) ----
        float a0 = 0.f, a1 = 0.f;
        #pragma unroll
        for (int jj = 0; jj < 16; jj++) {
            float4 hv0 = h40[jj];                   // LDS.128 broadcast
            float4 hv1 = h41[jj];                   // LDS.128 broadcast
            float2 f0 = __half22float2(*(const __half2*)&Wr[2 * jj]);
            float2 f1 = __half22float2(*(const __half2*)&Wr[2 * jj + 1]);
            a0 = fmaf(hv0.x, f0.x, a0);
            a1 = fmaf(hv1.x, f0.x, a1);
            a0 = fmaf(hv0.y, f0.y, a0);
            a1 = fmaf(hv1.y, f0.y, a1);
            a0 = fmaf(hv0.z, f1.x, a0);
            a1 = fmaf(hv1.z, f1.x, a1);
            a0 = fmaf(hv0.w, f1.y, a0);
            a1 = fmaf(hv1.w, f1.y, a1);
        }
        gph[kh][0][u] = a0;
        gph[kh][1][u] = a1;

        // ---- Phase 1b: attention lookup (warps 8..15) ----
        if (t >= 256 && t < 512) {
            int tt = t - 256;
            int m = tt >> 7, d2 = tt & 127;
            float h = h_s[m][d2];
            float uu = fmaf(h, (float)(TN / 2), (float)(TN / 2));
            int i = (int)uu;
            i = max(0, min(i, TN - 1));
            float f = uu - (float)i;
            float4 tv = Ttab[m][i];
            float gx = fmaf(f, tv.z, tv.x);
            float gy = fmaf(f, tv.w, tv.y);
            #pragma unroll
            for (int off = 16; off; off >>= 1) {
                gx += __shfl_xor_sync(0xffffffffu, gx, off);
                gy += __shfl_xor_sync(0xffffffffu, gy, off);
            }
            if (lane == 0) wred[m][(warp - 8) & 3] = make_float2(gx, gy);
        }
        __syncthreads();                         // B1

        // ---- Phase 2: ctx-combine + LSTM update (threads 0..255) ----
        if (t < 256) {
            int m = t >> 7, d = t & 127;
            float2 r0 = wred[m][0], r1 = wred[m][1], r2 = wred[m][2], r3 = wred[m][3];
            float x0c = (r0.x + r1.x + r2.x + r3.x) * (1.f / 128.f);
            float x1c = (r0.y + r1.y + r2.y + r3.y) * (1.f / 128.f);
            float2 wi0 = wihs[d];
            float2 wi1 = wihs[d + 128];
            float2 wi2 = wihs[d + 256];
            float2 wi3 = wihs[d + 384];
            float gi = gph[0][m][d]       + gph[1][m][d]       + sbias[d]
                     + x0c * wi0.x + x1c * wi0.y;
            float gf = gph[0][m][d + 128] + gph[1][m][d + 128] + sbias[d + 128]
                     + x0c * wi1.x + x1c * wi1.y;
            float gg = gph[0][m][d + 256] + gph[1][m][d + 256] + sbias[d + 256]
                     + x0c * wi2.x + x1c * wi2.y;
            float go = gph[0][m][d + 384] + gph[1][m][d + 384] + sbias[d + 384]
                     + x0c * wi3.x + x1c * wi3.y;
            float si = sigmoid_fast(gi);
            float sf = sigmoid_fast(gf);
            float so = sigmoid_fast(go);
            c_reg = fmaf(sf, c_reg, si * tanh_fast(gg));
            h_reg = so * tanh_fast(c_reg);
            h_s[m][d] = h_reg;
            out[(size_t)step * (BB * DD) + (2 * bid + m) * DD + d] = h_reg;
        }
        __syncthreads();                         // B2
    }
}

// ---------------------------------------------------------------------------
extern "C" void kernel_launch(void* const* d_in, const int* in_sizes, int n_in,
                              void* d_out, int out_size) {
    const float* enc  = (const float*)d_in[0];
    const float* W1_w = (const float*)d_in[1];
    const float* W1_b = (const float*)d_in[2];
    const float* W2_w = (const float*)d_in[3];
    const float* W2_b = (const float*)d_in[4];
    const float* W_ih = (const float*)d_in[5];
    const float* W_hh = (const float*)d_in[6];
    const float* b_ih = (const float*)d_in[7];
    const float* b_hh = (const float*)d_in[8];
    float* out = (float*)d_out;

    prep_kernel<<<129, 256>>>(W1_w, W_hh, b_ih, b_hh);
    decoder_kernel<<<BB / 2, 1024>>>(enc, W1_b, W2_w, W2_b, W_ih, out);
}